// round 6
// baseline (speedup 1.0000x reference)
#include <cuda_runtime.h>
#include <cstdint>

// Problem shapes (fixed by the dataset)
constexpr int B  = 8;
constexpr int H  = 512, W  = 512;
constexpr int HO = 1024, WO = 1024;
constexpr int FPY = 514;             // padded rows: y coords -1..512
constexpr int FPX = 516;             // padded row stride (float4-aligned)
constexpr int TPR = 129;             // fix col-groups per row (129*4 = 516)
constexpr int NPIX = B * HO * WO;    // 8388608 output pixels

constexpr int RPT    = 4;
constexpr int STRIPS = (FPY + RPT - 1) / RPT;   // 129
constexpr int NFIXT  = B * STRIPS * TPR;

// ---- sample kernel tiling ----
constexpr int TILE    = 1024;                   // pixels per tile
constexpr int NTILES  = NPIX / TILE;            // 8192 (1<<20 % TILE == 0: tiles never span batches)
constexpr int STHREADS = 256;
constexpr int PPT     = TILE / STHREADS;        // 4 pixels/thread/tile
constexpr int NCTAS   = 888;                    // ~6/SM
// smem: gbuf[2][TILE] float2 (16KB) | obuf[2][TILE] float (8KB) | 2 mbarriers
constexpr int SM_OBUF = 2 * TILE * 8;           // 16384
constexpr int SM_BAR  = SM_OBUF + 2 * TILE * 4; // 24576
constexpr int SM_SIZE = SM_BAR + 16;

// Precomputed "fixed" depth map, padded domain. 8.49 MB (L2-resident).
__device__ float4 g_fix4[B * FPY * (FPX / 4)];

// ---------------- pass 1: fix map ----------------
__device__ __forceinline__ void load_row6(const float* __restrict__ img, int row,
                                          int px0, float v[6]) {
    if ((unsigned)row >= (unsigned)H) {
        v[0] = v[1] = v[2] = v[3] = v[4] = v[5] = 0.0f;
        return;
    }
    const float* rp = img + row * W;
    if (px0 >= 4 && px0 <= 508) {
        float4 a = *(const float4*)(rp + px0 - 4);
        float4 b = *(const float4*)(rp + px0);
        v[0] = a.z; v[1] = a.w;
        v[2] = b.x; v[3] = b.y; v[4] = b.z; v[5] = b.w;
    } else {
#pragma unroll
        for (int i = 0; i < 6; i++) {
            int c = px0 - 2 + i;
            v[i] = ((unsigned)c < (unsigned)W) ? __ldg(rp + c) : 0.0f;
        }
    }
}

// First-valid among 9 offsets, reference order:
// (0,0), (-1,-1),(-1,0),(-1,1),(0,-1),(0,1),(1,-1),(1,0),(1,1)
__global__ void __launch_bounds__(256) fix_kernel(const float* __restrict__ depth) {
    int idx = blockIdx.x * blockDim.x + threadIdx.x;
    if (idx >= NFIXT) return;
    int t     = idx % TPR;
    int rest  = idx / TPR;
    int strip = rest % STRIPS;
    int b     = rest / STRIPS;
    int px0   = t * 4;
    int py0   = strip * RPT;
    int y0    = py0 - 1;

    const float* img = depth + b * (H * W);

    float rm[6], r0[6], rp[6];
    load_row6(img, y0 - 1, px0, rm);
    load_row6(img, y0,     px0, r0);

#pragma unroll
    for (int r = 0; r < RPT; r++) {
        int py = py0 + r;
        load_row6(img, y0 + r + 1, px0, rp);
        if (py < FPY) {
            float4 o;
            float* op = &o.x;
#pragma unroll
            for (int j = 0; j < 4; j++) {
                float c[9] = { r0[j + 1],
                               rm[j], rm[j + 1], rm[j + 2],
                               r0[j],            r0[j + 2],
                               rp[j], rp[j + 1], rp[j + 2] };
                float v = 0.0f;
#pragma unroll
                for (int k = 8; k >= 0; k--) {
                    if (c[k] != 0.0f) v = c[k];
                }
                op[j] = v;
            }
            g_fix4[(b * FPY + py) * (FPX / 4) + t] = o;
        }
#pragma unroll
        for (int i = 0; i < 6; i++) { rm[i] = r0[i]; r0[i] = rp[i]; }
    }
}

// ---------------- pass 2: TMA-streamed sampler ----------------
__device__ __forceinline__ uint32_t smem_u32(const void* p) {
    uint32_t a;
    asm("{ .reg .u64 t; cvta.to.shared.u64 t, %1; cvt.u32.u64 %0, t; }" : "=r"(a) : "l"(p));
    return a;
}
__device__ __forceinline__ void mbar_init(uint32_t m, uint32_t n) {
    asm volatile("mbarrier.init.shared.b64 [%0], %1;" :: "r"(m), "r"(n) : "memory");
}
__device__ __forceinline__ void mbar_expect_tx(uint32_t m, uint32_t bytes) {
    asm volatile("mbarrier.arrive.expect_tx.shared.b64 _, [%0], %1;" :: "r"(m), "r"(bytes) : "memory");
}
__device__ __forceinline__ void mbar_wait(uint32_t m, uint32_t parity) {
    uint32_t done;
    asm volatile(
        "{\n\t.reg .pred p;\n\t"
        "mbarrier.try_wait.parity.acquire.cta.shared::cta.b64 p, [%1], %2;\n\t"
        "selp.b32 %0, 1, 0, p;\n\t}"
        : "=r"(done) : "r"(m), "r"(parity) : "memory");
    if (!done) {
        asm volatile(
            "{\n\t.reg .pred P1;\n\t"
            "WL_%=:\n\t"
            "mbarrier.try_wait.parity.acquire.cta.shared::cta.b64 P1, [%0], %1, 0x989680;\n\t"
            "@P1 bra.uni WD_%=;\n\t"
            "bra.uni WL_%=;\n\t"
            "WD_%=:\n\t}"
            :: "r"(m), "r"(parity) : "memory");
    }
}
__device__ __forceinline__ void bulk_load(uint32_t dst, const void* src, uint32_t bytes,
                                          uint32_t mbar) {
    asm volatile("cp.async.bulk.shared::cta.global.mbarrier::complete_tx::bytes [%0], [%1], %2, [%3];"
                 :: "r"(dst), "l"(src), "r"(bytes), "r"(mbar) : "memory");
}
__device__ __forceinline__ void bulk_store(void* dst, uint32_t src, uint32_t bytes) {
    asm volatile("cp.async.bulk.global.shared::cta.bulk_group [%0], [%1], %2;"
                 :: "l"(dst), "r"(src), "r"(bytes) : "memory");
}

__global__ void __launch_bounds__(STHREADS)
sample_kernel(const float2* __restrict__ grid, float* __restrict__ out) {
    extern __shared__ char smem[];
    float2* gbuf = (float2*)smem;                 // [2][TILE]
    float*  obuf = (float*)(smem + SM_OBUF);      // [2][TILE]
    uint32_t bar0 = smem_u32(smem + SM_BAR);
    uint32_t bar1 = bar0 + 8;

    int tid = threadIdx.x;
    if (tid == 0) {
        mbar_init(bar0, 1);
        mbar_init(bar1, 1);
        // prologue: fill both input buffers
        int t0 = blockIdx.x;
        if (t0 < NTILES) {
            mbar_expect_tx(bar0, TILE * 8);
            bulk_load(smem_u32(gbuf), grid + (long)t0 * TILE, TILE * 8, bar0);
        }
        int t1 = t0 + NCTAS;
        if (t1 < NTILES) {
            mbar_expect_tx(bar1, TILE * 8);
            bulk_load(smem_u32(gbuf + TILE), grid + (long)t1 * TILE, TILE * 8, bar1);
        }
    }
    __syncthreads();

    int phase0 = 0, phase1 = 0;
    int k = 0;
    for (int t = blockIdx.x; t < NTILES; t += NCTAS, k++) {
        int p = k & 1;
        if (p == 0) { mbar_wait(bar0, phase0); phase0 ^= 1; }
        else        { mbar_wait(bar1, phase1); phase1 ^= 1; }

        int b = t >> 10;                         // (t*TILE)>>20
        const float* fixp = (const float*)g_fix4 + b * (FPY * FPX);

        float2 c[PPT];
#pragma unroll
        for (int i = 0; i < PPT; i++) c[i] = gbuf[p * TILE + tid + i * STHREADS];

        float v[PPT];
#pragma unroll
        for (int i = 0; i < PPT; i++) {
            // ((g+1)*0.5)*511 == round_fp32(g+1)*255.5 exactly (×0.5 exact);
            // __float2int_rn = ties-to-even = jnp.round
            float xf = __fmul_rn(__fadd_rn(c[i].x, 1.0f), 255.5f);
            float yf = __fmul_rn(__fadd_rn(c[i].y, 1.0f), 255.5f);
            int ix = __float2int_rn(xf) + 1;     // padded coords
            int iy = __float2int_rn(yf) + 1;
            bool inb = ((unsigned)ix < 514u) & ((unsigned)iy < 514u);
            v[i] = inb ? __ldg(fixp + iy * FPX + ix) : 0.0f;
        }

#pragma unroll
        for (int i = 0; i < PPT; i++) obuf[p * TILE + tid + i * STHREADS] = v[i];
        __syncthreads();                          // STS visible; LDS of gbuf[p] done

        if (tid == 0) {
            asm volatile("fence.proxy.async.shared::cta;" ::: "memory");
            bulk_store(out + (long)t * TILE, smem_u32(obuf + p * TILE), TILE * 4);
            asm volatile("cp.async.bulk.commit_group;" ::: "memory");
            int tn = t + 2 * NCTAS;               // refill this input buffer
            if (tn < NTILES) {
                uint32_t bb = p ? bar1 : bar0;
                mbar_expect_tx(bb, TILE * 8);
                bulk_load(smem_u32(gbuf + p * TILE), grid + (long)tn * TILE, TILE * 8, bb);
            }
            // the store issued LAST iteration (into the other obuf) must finish
            // before that buffer's STS next iteration
            asm volatile("cp.async.bulk.wait_group 1;" ::: "memory");
        }
        __syncthreads();                          // all threads see wait_group done
    }
    if (tid == 0) asm volatile("cp.async.bulk.wait_group 0;" ::: "memory");
}

extern "C" void kernel_launch(void* const* d_in, const int* in_sizes, int n_in,
                              void* d_out, int out_size) {
    const float*  depth = (const float*)d_in[0];   // (B,1,H,W) f32
    const float2* grid  = (const float2*)d_in[1];  // (B,Ho,Wo,2) f32
    float*        out   = (float*)d_out;           // (B,1,Ho,Wo) f32

    cudaFuncSetAttribute(sample_kernel, cudaFuncAttributeMaxDynamicSharedMemorySize, SM_SIZE);

    fix_kernel<<<(NFIXT + 255) / 256, 256>>>(depth);
    sample_kernel<<<NCTAS, STHREADS, SM_SIZE>>>(grid, out);
}

// round 7
// speedup vs baseline: 1.4943x; 1.4943x over previous
#include <cuda_runtime.h>

// Problem shapes (fixed by the dataset)
constexpr int B  = 8;
constexpr int H  = 512, W  = 512;
constexpr int HO = 1024, WO = 1024;
constexpr int FPY = 514;             // padded rows: y coords -1..512
constexpr int FPX = 516;             // padded row stride (514 valid + 2 pad, float4-aligned)
constexpr int TPR = 129;             // fix col-groups per row (129*4 = 516)
constexpr int NPIX = B * HO * WO;    // 8388608 output pixels
constexpr int NQUAD = NPIX / 4;      // 2097152 = 2^21 output quads

constexpr int RPT    = 4;                      // fix rows per thread (rolling window)
constexpr int STRIPS = (FPY + RPT - 1) / RPT;  // 129
constexpr int NFIXT  = B * STRIPS * TPR;

// Exact balance: 2048 CTAs * 256 thr = 2^19 threads * 4 quads = 2^21 = NQUAD.
constexpr int SCTAS   = 2048;
constexpr int STH     = 256;
constexpr int SSTRIDE = SCTAS * STH;           // 524288
constexpr int SITERS  = NQUAD / SSTRIDE;       // 4, exact

// Precomputed "fixed" depth map, padded domain. 8*514*516*4 B = 8.49 MB (L2-resident).
__device__ float4 g_fix4[B * FPY * (FPX / 4)];

// ---------------- pass 1: fix map ----------------
// Load 6 input floats covering columns [px0-2, px0+3] of `row` (0 if OOB).
__device__ __forceinline__ void load_row6(const float* __restrict__ img, int row,
                                          int px0, float v[6]) {
    if ((unsigned)row >= (unsigned)H) {
        v[0] = v[1] = v[2] = v[3] = v[4] = v[5] = 0.0f;
        return;
    }
    const float* rp = img + row * W;
    if (px0 >= 4 && px0 <= 508) {
        float4 a = *(const float4*)(rp + px0 - 4);
        float4 b = *(const float4*)(rp + px0);
        v[0] = a.z; v[1] = a.w;
        v[2] = b.x; v[3] = b.y; v[4] = b.z; v[5] = b.w;
    } else {
#pragma unroll
        for (int i = 0; i < 6; i++) {
            int c = px0 - 2 + i;
            v[i] = ((unsigned)c < (unsigned)W) ? __ldg(rp + c) : 0.0f;
        }
    }
}

// First-valid among 9 offsets, reference order:
// (0,0), (-1,-1),(-1,0),(-1,1),(0,-1),(0,1),(1,-1),(1,0),(1,1)
// Each thread: 4 columns x RPT rows with a 3-row rolling window.
__global__ void __launch_bounds__(256) fix_kernel(const float* __restrict__ depth) {
    int idx = blockIdx.x * blockDim.x + threadIdx.x;
    if (idx >= NFIXT) return;
    int t     = idx % TPR;
    int rest  = idx / TPR;
    int strip = rest % STRIPS;
    int b     = rest / STRIPS;
    int px0   = t * 4;
    int py0   = strip * RPT;
    int y0    = py0 - 1;

    const float* img = depth + b * (H * W);

    float rm[6], r0[6], rp[6];
    load_row6(img, y0 - 1, px0, rm);
    load_row6(img, y0,     px0, r0);

#pragma unroll
    for (int r = 0; r < RPT; r++) {
        int py = py0 + r;
        load_row6(img, y0 + r + 1, px0, rp);
        if (py < FPY) {
            float4 o;
            float* op = &o.x;
#pragma unroll
            for (int j = 0; j < 4; j++) {
                float c[9] = { r0[j + 1],
                               rm[j], rm[j + 1], rm[j + 2],
                               r0[j],            r0[j + 2],
                               rp[j], rp[j + 1], rp[j + 2] };
                float v = 0.0f;
#pragma unroll
                for (int k = 8; k >= 0; k--) {
                    if (c[k] != 0.0f) v = c[k];   // first-valid via reverse last-write
                }
                op[j] = v;
            }
            g_fix4[(b * FPY + py) * (FPX / 4) + t] = o;
        }
#pragma unroll
        for (int i = 0; i < 6; i++) { rm[i] = r0[i]; r0[i] = rp[i]; }
    }
}

// ---------------- pass 2: sampler ----------------
// 4 independent gathers for quad q; grid values ga,gb.
__device__ __forceinline__ void issue_quad(int q, float4 ga, float4 gb, float v[4]) {
    int b = q >> 18;                          // quads never span batches (HO*WO = 1<<20)
    const float* fixp = (const float*)g_fix4 + b * (FPY * FPX);
    float gx[4] = {ga.x, ga.z, gb.x, gb.z};
    float gy[4] = {ga.y, ga.w, gb.y, gb.w};
#pragma unroll
    for (int i = 0; i < 4; i++) {
        // ((g+1)*0.5)*511 == round_fp32(g+1) * 255.5 exactly (×0.5 exact);
        // __float2int_rn = ties-to-even = jnp.round
        float xf = __fmul_rn(__fadd_rn(gx[i], 1.0f), 255.5f);
        float yf = __fmul_rn(__fadd_rn(gy[i], 1.0f), 255.5f);
        int ix = __float2int_rn(xf) + 1;      // padded coords
        int iy = __float2int_rn(yf) + 1;
        bool inb = ((unsigned)ix < 514u) & ((unsigned)iy < 514u);
        v[i] = inb ? __ldg(fixp + iy * FPX + ix) : 0.0f;
    }
}

// Exactly SITERS quads/thread, fully unrolled, no bounds checks; grid for the
// next iteration is prefetched while the current 4 gathers are in flight.
// In-flight gathers per warp stays at 4 (per the R3/R5 L1tex-queue evidence).
__global__ void __launch_bounds__(STH)
sample_kernel(const float4* __restrict__ grid, float4* __restrict__ out) {
    int q0 = blockIdx.x * STH + threadIdx.x;

    float4 ga = __ldcs(grid + 2 * q0);
    float4 gb = __ldcs(grid + 2 * q0 + 1);

#pragma unroll
    for (int i = 0; i < SITERS; i++) {
        int q = q0 + i * SSTRIDE;
        float4 na, nb;
        if (i + 1 < SITERS) {
            na = __ldcs(grid + 2 * (q + SSTRIDE));
            nb = __ldcs(grid + 2 * (q + SSTRIDE) + 1);
        }
        float v[4];
        issue_quad(q, ga, gb, v);
        float4 o = {v[0], v[1], v[2], v[3]};
        __stcs(out + q, o);
        ga = na; gb = nb;
    }
}

extern "C" void kernel_launch(void* const* d_in, const int* in_sizes, int n_in,
                              void* d_out, int out_size) {
    const float*  depth = (const float*)d_in[0];   // (B,1,H,W) f32
    const float4* grid  = (const float4*)d_in[1];  // (B,Ho,Wo,2) f32 as float4
    float4*       out   = (float4*)d_out;          // (B,1,Ho,Wo) f32 as float4

    fix_kernel<<<(NFIXT + 255) / 256, 256>>>(depth);
    sample_kernel<<<SCTAS, STH>>>(grid, out);
}